// round 4
// baseline (speedup 1.0000x reference)
#include <cuda_runtime.h>
#include <math.h>

// Problem constants
#define B_   8
#define C_   512
#define HW_  1024
#define D_   512
#define NH_  8
#define HD_  64
#define L_   77
#define DC_  768
#define FF_  2048
#define M_   (B_ * HW_)   // 8192 tokens

// ---------------- scratch (no allocation allowed -> __device__ globals) ----
__device__ float g_H[(size_t)M_ * D_];   // running hidden state
__device__ float g_X[(size_t)M_ * D_];   // GN / LN outputs
__device__ float g_Q[(size_t)M_ * D_];
__device__ float g_K[(size_t)M_ * D_];
__device__ float g_V[(size_t)M_ * D_];
__device__ float g_A[(size_t)M_ * D_];   // attention output
__device__ float g_F[(size_t)M_ * FF_];  // FF hidden

// ---------------------------------------------------------------- GroupNorm
// x: [B, C, H*W], 32 groups x 16 ch. Output transposed: out[(b*HW + s)*C + c]
__global__ __launch_bounds__(256) void groupnorm_kernel(
    const float* __restrict__ x, const float* __restrict__ gam,
    const float* __restrict__ bet, float* __restrict__ out)
{
    const int b = blockIdx.x >> 5;
    const int g = blockIdx.x & 31;
    const int CPG = 16;
    const float* base = x + ((size_t)(b * C_ + g * CPG)) * HW_;  // contiguous 16*1024
    const int tid = threadIdx.x;

    float s = 0.f, ss = 0.f;
    for (int i = tid; i < CPG * HW_; i += 256) {
        float v = base[i];
        s += v; ss += v * v;
    }
    __shared__ float red[256], red2[256];
    red[tid] = s; red2[tid] = ss;
    __syncthreads();
    for (int st = 128; st > 0; st >>= 1) {
        if (tid < st) { red[tid] += red[tid + st]; red2[tid] += red2[tid + st]; }
        __syncthreads();
    }
    __shared__ float s_mu, s_rstd;
    if (tid == 0) {
        float mu  = red[0] / (CPG * HW_);
        float var = red2[0] / (CPG * HW_) - mu * mu;
        s_mu = mu;
        s_rstd = rsqrtf(var + 1e-5f);
    }
    __shared__ float gv[16], bv[16];
    if (tid < 16) { gv[tid] = gam[g * CPG + tid]; bv[tid] = bet[g * CPG + tid]; }
    __syncthreads();
    const float mu = s_mu, rstd = s_rstd;

    __shared__ float tile[16][65];
    for (int s0 = 0; s0 < HW_; s0 += 64) {
        for (int i = tid; i < 16 * 64; i += 256) {
            int c = i >> 6, sp = i & 63;
            tile[c][sp] = base[(size_t)c * HW_ + s0 + sp];
        }
        __syncthreads();
        for (int i = tid; i < 16 * 64; i += 256) {
            int c = i & 15, sp = i >> 4;
            float v = (tile[c][sp] - mu) * rstd * gv[c] + bv[c];
            out[((size_t)(b * HW_ + s0 + sp)) * C_ + g * CPG + c] = v;
        }
        __syncthreads();
    }
}

// ---------------------------------------------------------------- LayerNorm
// rows of 512, one warp per row
__global__ __launch_bounds__(256) void layernorm_kernel(
    const float* __restrict__ in, const float* __restrict__ g,
    const float* __restrict__ b, float* __restrict__ out)
{
    const int row  = blockIdx.x * 8 + (threadIdx.x >> 5);
    const int lane = threadIdx.x & 31;
    const float4* ip = (const float4*)(in + (size_t)row * D_);
    float4 v[4];
    float s = 0.f, ss = 0.f;
#pragma unroll
    for (int i = 0; i < 4; i++) {
        v[i] = ip[lane + 32 * i];
        s  += v[i].x + v[i].y + v[i].z + v[i].w;
        ss += v[i].x*v[i].x + v[i].y*v[i].y + v[i].z*v[i].z + v[i].w*v[i].w;
    }
#pragma unroll
    for (int o = 16; o > 0; o >>= 1) {
        s  += __shfl_xor_sync(0xffffffffu, s, o);
        ss += __shfl_xor_sync(0xffffffffu, ss, o);
    }
    const float mu   = s * (1.f / D_);
    const float rstd = rsqrtf(ss * (1.f / D_) - mu * mu + 1e-5f);
    const float4* gp = (const float4*)g;
    const float4* bp = (const float4*)b;
    float4* op = (float4*)(out + (size_t)row * D_);
#pragma unroll
    for (int i = 0; i < 4; i++) {
        float4 gg = gp[lane + 32 * i], bb = bp[lane + 32 * i], o4;
        o4.x = (v[i].x - mu) * rstd * gg.x + bb.x;
        o4.y = (v[i].y - mu) * rstd * gg.y + bb.y;
        o4.z = (v[i].z - mu) * rstd * gg.z + bb.z;
        o4.w = (v[i].w - mu) * rstd * gg.w + bb.w;
        op[lane + 32 * i] = o4;
    }
}

// -------------------------------------------------------------------- GEMM
// out[M,N] = A[M,K] @ W[K,N] (+bias) with epilogue:
//   mode 0: bias only; mode 1: bias + exact GELU; mode 2: bias + resid add
//   mode 3: final: out[(b*C + n)*HW + hw] = acc + bias[n] + resid[same] (BCHW)
// 128x128x16 tile, 8x8 microtile, 256 threads, split fragments (f, 64+f).
__global__ __launch_bounds__(256) void gemm_kernel(
    const float* __restrict__ A, const float* __restrict__ W,
    const float* __restrict__ bias, const float* __restrict__ resid,
    float* __restrict__ out, int M, int N, int K, int mode)
{
    __shared__ float As[16][136];   // [k][m], padded, 16B-aligned rows
    __shared__ float Bs[16][128];   // [k][n]
    const int m0 = blockIdx.y * 128;
    const int n0 = blockIdx.x * 128;
    const int tid = threadIdx.x;
    const int tx = tid & 15, ty = tid >> 4;   // 16 x 16
    float acc[8][8] = {};

    for (int k0 = 0; k0 < K; k0 += 16) {
        // A: 128 rows x 16 k = 512 float4, 2 per thread, store transposed
#pragma unroll
        for (int i = 0; i < 2; i++) {
            int f4 = tid * 2 + i;            // 0..511
            int mm = f4 >> 2;                // 0..127
            int kk = (f4 & 3) * 4;           // 0,4,8,12
            int m  = m0 + mm;
            float4 v = make_float4(0.f, 0.f, 0.f, 0.f);
            if (m < M) v = *(const float4*)(A + (size_t)m * K + k0 + kk);
            As[kk + 0][mm] = v.x;
            As[kk + 1][mm] = v.y;
            As[kk + 2][mm] = v.z;
            As[kk + 3][mm] = v.w;
        }
        // B: 16 rows x 128 n = 512 float4, 2 per thread
#pragma unroll
        for (int i = 0; i < 2; i++) {
            int f4 = tid * 2 + i;
            int kk = f4 >> 5;                // 0..15
            int nn = (f4 & 31) * 4;          // 0..124
            *(float4*)&Bs[kk][nn] =
                *(const float4*)(W + (size_t)(k0 + kk) * N + n0 + nn);
        }
        __syncthreads();
#pragma unroll
        for (int kk = 0; kk < 16; kk++) {
            float a[8], b[8];
            *(float4*)&a[0] = *(float4*)&As[kk][ty * 4];
            *(float4*)&a[4] = *(float4*)&As[kk][64 + ty * 4];
            *(float4*)&b[0] = *(float4*)&Bs[kk][tx * 4];
            *(float4*)&b[4] = *(float4*)&Bs[kk][64 + tx * 4];
#pragma unroll
            for (int i = 0; i < 8; i++)
#pragma unroll
                for (int j = 0; j < 8; j++) acc[i][j] += a[i] * b[j];
        }
        __syncthreads();
    }

    // row i -> m = m0 + (i<4 ? ty*4+i : 64+ty*4+i-4); col j analogous with tx.
    if (mode == 3) {
        const int b   = m0 >> 10;
        const int hw0 = m0 & 1023;
#pragma unroll
        for (int j = 0; j < 8; j++) {
            int n = n0 + (j < 4 ? tx * 4 + j : 64 + tx * 4 + (j - 4));
            float bj = bias[n];
            size_t col = ((size_t)(b * C_ + n)) * HW_ + hw0;
#pragma unroll
            for (int h = 0; h < 2; h++) {
                int r = h * 64 + ty * 4;
                float4 rv = *(const float4*)(resid + col + r);
                float4 ov;
                ov.x = acc[h * 4 + 0][j] + bj + rv.x;
                ov.y = acc[h * 4 + 1][j] + bj + rv.y;
                ov.z = acc[h * 4 + 2][j] + bj + rv.z;
                ov.w = acc[h * 4 + 3][j] + bj + rv.w;
                *(float4*)(out + col + r) = ov;
            }
        }
    } else {
        float bv[8];
#pragma unroll
        for (int j = 0; j < 8; j++) {
            int n = n0 + (j < 4 ? tx * 4 + j : 64 + tx * 4 + (j - 4));
            bv[j] = bias ? bias[n] : 0.f;
        }
#pragma unroll
        for (int i = 0; i < 8; i++) {
            int m = m0 + (i < 4 ? ty * 4 + i : 64 + ty * 4 + (i - 4));
            if (m >= M) continue;
            float v[8];
#pragma unroll
            for (int j = 0; j < 8; j++) {
                v[j] = acc[i][j] + bv[j];
                if (mode == 1)
                    v[j] = 0.5f * v[j] *
                           (1.f + erff(v[j] * 0.70710678118654752f));
            }
            size_t rowb = (size_t)m * N + n0;
            if (mode == 2) {
                float4 r0 = *(const float4*)(resid + rowb + tx * 4);
                float4 r1 = *(const float4*)(resid + rowb + 64 + tx * 4);
                v[0] += r0.x; v[1] += r0.y; v[2] += r0.z; v[3] += r0.w;
                v[4] += r1.x; v[5] += r1.y; v[6] += r1.z; v[7] += r1.w;
            }
            *(float4*)(out + rowb + tx * 4)      = make_float4(v[0], v[1], v[2], v[3]);
            *(float4*)(out + rowb + 64 + tx * 4) = make_float4(v[4], v[5], v[6], v[7]);
        }
    }
}

// -------------------------------------------------------- Flash attention
// Q: [B, HW, D] (heads packed), K/V: [B, Lkv, D]. One block per (qtile, h, b).
#define ATTN_SMEM_BYTES ((4 * 64 * 65 + 3 * 64) * (int)sizeof(float))

__global__ __launch_bounds__(256) void attn_kernel(
    const float* __restrict__ Q, const float* __restrict__ K,
    const float* __restrict__ V, float* __restrict__ O, int Lkv)
{
    extern __shared__ float sm[];
    float* Qs   = sm;                 // [64][65]
    float* Ks   = Qs + 64 * 65;
    float* Vs   = Ks + 64 * 65;
    float* Ps   = Vs + 64 * 65;
    float* mrow = Ps + 64 * 65;       // [64]
    float* lrow = mrow + 64;
    float* arow = lrow + 64;

    const int q0  = blockIdx.x * 64;
    const int h   = blockIdx.y;
    const int b   = blockIdx.z;
    const int tid = threadIdx.x;
    const int tx  = tid & 15, ty = tid >> 4;
    const float scale = 0.125f;  // 64^-0.5

    for (int i = tid; i < 4096; i += 256) {
        int qq = i >> 6, d = i & 63;
        Qs[qq * 65 + d] = Q[((size_t)(b * HW_ + q0 + qq)) * D_ + h * HD_ + d] * scale;
    }
    if (tid < 64) { mrow[tid] = -1e30f; lrow[tid] = 0.f; }
    float o[4][4] = {};
    __syncthreads();

    for (int j0 = 0; j0 < Lkv; j0 += 64) {
        for (int i = tid; i < 4096; i += 256) {
            int jj = i >> 6, d = i & 63;
            int j = j0 + jj;
            float kv = 0.f, vv = 0.f;
            if (j < Lkv) {
                size_t base = ((size_t)(b * Lkv + j)) * D_ + h * HD_ + d;
                kv = K[base]; vv = V[base];
            }
            Ks[jj * 65 + d] = kv;
            Vs[jj * 65 + d] = vv;
        }
        __syncthreads();

        // S = Q K^T (64x64), 4x4 per thread
        float s[4][4] = {};
#pragma unroll 8
        for (int d = 0; d < 64; d++) {
            float a[4], bb[4];
#pragma unroll
            for (int i = 0; i < 4; i++) a[i]  = Qs[(ty * 4 + i) * 65 + d];
#pragma unroll
            for (int j = 0; j < 4; j++) bb[j] = Ks[(tx * 4 + j) * 65 + d];
#pragma unroll
            for (int i = 0; i < 4; i++)
#pragma unroll
                for (int j = 0; j < 4; j++) s[i][j] += a[i] * bb[j];
        }
#pragma unroll
        for (int i = 0; i < 4; i++)
#pragma unroll
            for (int j = 0; j < 4; j++) {
                int jg = j0 + tx * 4 + j;
                Ps[(ty * 4 + i) * 65 + tx * 4 + j] = (jg < Lkv) ? s[i][j] : -1e30f;
            }
        __syncthreads();

        // online softmax stats: 4 threads per row
        {
            const int r = tid >> 2, p = tid & 3;
            float cmax = -1e30f;
            for (int jj = p; jj < 64; jj += 4)
                cmax = fmaxf(cmax, Ps[r * 65 + jj]);
            cmax = fmaxf(cmax, __shfl_xor_sync(0xffffffffu, cmax, 1));
            cmax = fmaxf(cmax, __shfl_xor_sync(0xffffffffu, cmax, 2));
            float mold = mrow[r];
            float mnew = fmaxf(mold, cmax);
            float csum = 0.f;
            for (int jj = p; jj < 64; jj += 4) {
                float e = __expf(Ps[r * 65 + jj] - mnew);
                Ps[r * 65 + jj] = e;
                csum += e;
            }
            csum += __shfl_xor_sync(0xffffffffu, csum, 1);
            csum += __shfl_xor_sync(0xffffffffu, csum, 2);
            if (p == 0) {
                float al = __expf(mold - mnew);
                arow[r] = al;
                lrow[r] = lrow[r] * al + csum;
                mrow[r] = mnew;
            }
        }
        __syncthreads();

        // rescale accumulators, then O += P @ V
#pragma unroll
        for (int i = 0; i < 4; i++) {
            float al = arow[ty * 4 + i];
#pragma unroll
            for (int j = 0; j < 4; j++) o[i][j] *= al;
        }
#pragma unroll 8
        for (int jj = 0; jj < 64; jj++) {
            float p[4], vv[4];
#pragma unroll
            for (int i = 0; i < 4; i++) p[i]  = Ps[(ty * 4 + i) * 65 + jj];
#pragma unroll
            for (int j = 0; j < 4; j++) vv[j] = Vs[jj * 65 + tx * 4 + j];
#pragma unroll
            for (int i = 0; i < 4; i++)
#pragma unroll
                for (int j = 0; j < 4; j++) o[i][j] += p[i] * vv[j];
        }
        __syncthreads();
    }

#pragma unroll
    for (int i = 0; i < 4; i++) {
        float inv = 1.f / lrow[ty * 4 + i];
#pragma unroll
        for (int j = 0; j < 4; j++)
            O[((size_t)(b * HW_ + q0 + ty * 4 + i)) * D_ + h * HD_ + tx * 4 + j] =
                o[i][j] * inv;
    }
}

// ------------------------------------------------------------------ driver
extern "C" void kernel_launch(void* const* d_in, const int* in_sizes, int n_in,
                              void* d_out, int out_size)
{
    const float* x         = (const float*)d_in[0];
    const float* ctx       = (const float*)d_in[1];
    const float* gn_g      = (const float*)d_in[2];
    const float* gn_b      = (const float*)d_in[3];
    const float* proj_in_w = (const float*)d_in[4];
    const float* proj_in_b = (const float*)d_in[5];
    const float* ln1_g = (const float*)d_in[6];
    const float* ln1_b = (const float*)d_in[7];
    const float* q1_w  = (const float*)d_in[8];
    const float* k1_w  = (const float*)d_in[9];
    const float* v1_w  = (const float*)d_in[10];
    const float* o1_w  = (const float*)d_in[11];
    const float* o1_b  = (const float*)d_in[12];
    const float* ln2_g = (const float*)d_in[13];
    const float* ln2_b = (const float*)d_in[14];
    const float* q2_w  = (const float*)d_in[15];
    const float* k2_w  = (const float*)d_in[16];
    const float* v2_w  = (const float*)d_in[17];
    const float* o2_w  = (const float*)d_in[18];
    const float* o2_b  = (const float*)d_in[19];
    const float* ln3_g = (const float*)d_in[20];
    const float* ln3_b = (const float*)d_in[21];
    const float* ff1_w = (const float*)d_in[22];
    const float* ff1_b = (const float*)d_in[23];
    const float* ff2_w = (const float*)d_in[24];
    const float* ff2_b = (const float*)d_in[25];
    const float* po_w  = (const float*)d_in[26];
    const float* po_b  = (const float*)d_in[27];
    float* out = (float*)d_out;

    float *pH, *pX, *pQ, *pK, *pV, *pA, *pF;
    cudaGetSymbolAddress((void**)&pH, g_H);
    cudaGetSymbolAddress((void**)&pX, g_X);
    cudaGetSymbolAddress((void**)&pQ, g_Q);
    cudaGetSymbolAddress((void**)&pK, g_K);
    cudaGetSymbolAddress((void**)&pV, g_V);
    cudaGetSymbolAddress((void**)&pA, g_A);
    cudaGetSymbolAddress((void**)&pF, g_F);

    cudaFuncSetAttribute(attn_kernel,
                         cudaFuncAttributeMaxDynamicSharedMemorySize,
                         ATTN_SMEM_BYTES);

    const dim3 g512(D_ / 128, M_ / 128);                  // 4 x 64
    const dim3 gctx(D_ / 128, (B_ * L_ + 127) / 128);     // 4 x 5
    const dim3 gff(FF_ / 128, M_ / 128);                  // 16 x 64
    const dim3 gattn(HW_ / 64, NH_, B_);

    // GroupNorm -> X (transposed [B*HW, C])
    groupnorm_kernel<<<B_ * 32, 256>>>(x, gn_g, gn_b, pX);
    // proj_in
    gemm_kernel<<<g512, 256>>>(pX, proj_in_w, proj_in_b, nullptr, pH, M_, D_, C_, 0);

    // --- self attention ---
    layernorm_kernel<<<M_ / 8, 256>>>(pH, ln1_g, ln1_b, pX);
    gemm_kernel<<<g512, 256>>>(pX, q1_w, nullptr, nullptr, pQ, M_, D_, D_, 0);
    gemm_kernel<<<g512, 256>>>(pX, k1_w, nullptr, nullptr, pK, M_, D_, D_, 0);
    gemm_kernel<<<g512, 256>>>(pX, v1_w, nullptr, nullptr, pV, M_, D_, D_, 0);
    attn_kernel<<<gattn, 256, ATTN_SMEM_BYTES>>>(pQ, pK, pV, pA, HW_);
    gemm_kernel<<<g512, 256>>>(pA, o1_w, o1_b, pH, pH, M_, D_, D_, 2);  // +resid

    // --- cross attention ---
    layernorm_kernel<<<M_ / 8, 256>>>(pH, ln2_g, ln2_b, pX);
    gemm_kernel<<<g512, 256>>>(pX, q2_w, nullptr, nullptr, pQ, M_, D_, D_, 0);
    gemm_kernel<<<gctx, 256>>>(ctx, k2_w, nullptr, nullptr, pK, B_ * L_, D_, DC_, 0);
    gemm_kernel<<<gctx, 256>>>(ctx, v2_w, nullptr, nullptr, pV, B_ * L_, D_, DC_, 0);
    attn_kernel<<<gattn, 256, ATTN_SMEM_BYTES>>>(pQ, pK, pV, pA, L_);
    gemm_kernel<<<g512, 256>>>(pA, o2_w, o2_b, pH, pH, M_, D_, D_, 2);  // +resid

    // --- feed forward ---
    layernorm_kernel<<<M_ / 8, 256>>>(pH, ln3_g, ln3_b, pX);
    gemm_kernel<<<gff, 256>>>(pX, ff1_w, ff1_b, nullptr, pF, M_, FF_, D_, 1);   // GELU
    gemm_kernel<<<g512, 256>>>(pF, ff2_w, ff2_b, pH, pH, M_, D_, FF_, 2);       // +resid

    // --- proj_out + input residual, write BCHW ---
    gemm_kernel<<<g512, 256>>>(pH, po_w, po_b, x, out, M_, D_, D_, 3);
}